// round 6
// baseline (speedup 1.0000x reference)
#include <cuda_runtime.h>
#include <cuda_fp16.h>
#include <cstdint>

// Problem constants
constexpr int B_ = 16384;
constexpr int E_ = 1024;
constexpr int H_ = 8;
constexpr int D_ = 128;

// ---------------------------------------------------------------------------
// Scratch (static device globals: allocation-free, graph-capture safe)
// ---------------------------------------------------------------------------
__device__ __half g_AB[2u * B_ * E_];           // [image; signal] fp16   (64 MB)
__device__ __half g_Wq[E_ * E_];                //                        ( 2 MB)
__device__ __half g_Wkv[2 * E_ * E_];           // [Wk; Wv] rows stacked  ( 4 MB)
__device__ __half g_Wo[E_ * E_];                //                        ( 2 MB)
__device__ __half g_Q[(size_t)B_ * E_];         //                        (32 MB)
__device__ __half g_KV[(size_t)2 * B_ * 2 * E_];// [2B, 2048]             (128 MB)
__device__ __half g_ctx[(size_t)B_ * E_];       //                        (32 MB)
__device__ float  g_fused[(size_t)B_ * E_];     // attn_out + residual    (64 MB)
__device__ float  g_bkv[2 * E_];                // [bk; bv]

// ---------------------------------------------------------------------------
// PTX helpers (sm_80-class only: cp.async / ldmatrix / mma.sync)
// ---------------------------------------------------------------------------
__device__ __forceinline__ uint32_t smem_u32(const void* p) {
    return (uint32_t)__cvta_generic_to_shared(p);
}
__device__ __forceinline__ void cp16(uint32_t s, const void* g) {
    asm volatile("cp.async.cg.shared.global [%0], [%1], 16;\n" :: "r"(s), "l"(g));
}
__device__ __forceinline__ void cp_commit() {
    asm volatile("cp.async.commit_group;\n");
}
template <int N>
__device__ __forceinline__ void cp_wait() {
    asm volatile("cp.async.wait_group %0;\n" :: "n"(N));
}
__device__ __forceinline__ void ldmatrix_x4(uint32_t* r, uint32_t addr) {
    asm volatile("ldmatrix.sync.aligned.m8n8.x4.shared.b16 {%0,%1,%2,%3}, [%4];\n"
                 : "=r"(r[0]), "=r"(r[1]), "=r"(r[2]), "=r"(r[3]) : "r"(addr));
}
__device__ __forceinline__ void mma16816(float* c, const uint32_t* a, const uint32_t* b) {
    asm volatile("mma.sync.aligned.m16n8k16.row.col.f32.f16.f16.f32 "
                 "{%0,%1,%2,%3}, {%4,%5,%6,%7}, {%8,%9}, {%0,%1,%2,%3};\n"
                 : "+f"(c[0]), "+f"(c[1]), "+f"(c[2]), "+f"(c[3])
                 : "r"(a[0]), "r"(a[1]), "r"(a[2]), "r"(a[3]), "r"(b[0]), "r"(b[1]));
}

// ---------------------------------------------------------------------------
// Single conversion kernel (inputs fp32->fp16, weights fp32->fp16, bkv copy)
// ---------------------------------------------------------------------------
constexpr int IN4 = (2 * B_ * E_) / 4;        // 8388608
constexpr int W4  = (4 * E_ * E_) / 4;        // 1048576
constexpr int BV4 = (2 * E_) / 4;             // 512
constexpr int CVT_TOT = IN4 + W4 + BV4;       // 9437696 (divisible by 256)

__global__ void k_convert_all(const float* __restrict__ img, const float* __restrict__ sig,
                              const float* __restrict__ wq, const float* __restrict__ wk,
                              const float* __restrict__ wv, const float* __restrict__ wo,
                              const float* __restrict__ bk, const float* __restrict__ bv) {
    int i = blockIdx.x * blockDim.x + threadIdx.x;
    if (i < IN4) {
        const int n4 = (B_ * E_) / 4;
        float4 v = (i < n4) ? reinterpret_cast<const float4*>(img)[i]
                            : reinterpret_cast<const float4*>(sig)[i - n4];
        __half* dst = g_AB + (size_t)4 * i;
        *reinterpret_cast<__half2*>(dst)     = __floats2half2_rn(v.x, v.y);
        *reinterpret_cast<__half2*>(dst + 2) = __floats2half2_rn(v.z, v.w);
    } else if (i < IN4 + W4) {
        int j = i - IN4;
        const int per = (E_ * E_) / 4;
        int m = j / per;
        int t = j - m * per;
        const float* src;
        __half* dst;
        if (m == 0)      { src = wq; dst = g_Wq; }
        else if (m == 1) { src = wk; dst = g_Wkv; }
        else if (m == 2) { src = wv; dst = g_Wkv + E_ * E_; }
        else             { src = wo; dst = g_Wo; }
        float4 v = reinterpret_cast<const float4*>(src)[t];
        dst += (size_t)4 * t;
        *reinterpret_cast<__half2*>(dst)     = __floats2half2_rn(v.x, v.y);
        *reinterpret_cast<__half2*>(dst + 2) = __floats2half2_rn(v.z, v.w);
    } else {
        int j = i - IN4 - W4;                 // 0..511, each copies 4 floats
        int base = 4 * j;
        float4 v = (base < E_) ? reinterpret_cast<const float4*>(bk)[j]
                               : reinterpret_cast<const float4*>(bv)[j - E_ / 4];
        *reinterpret_cast<float4*>(&g_bkv[base]) = v;
    }
}

// ---------------------------------------------------------------------------
// Shared GEMM core: C[*, cl] = A[M,1024] * W[128 rows,1024]^T (NT), fp16->fp32.
// CTA tile 128x128x64, 3-stage cp.async, 8 warps (2M x 4N), warp 64x32.
// B fragments double-buffered across kk: B(kk+1) LDSM issued before kk's MMAs,
// so crossbar traffic overlaps tensor work. A fragments JIT per (kk, am).
// EPI=0: half out  = acc + bias[cl]
// EPI=1: float out = acc + bias[cl] + resid[row*ldOut+cl]
// ---------------------------------------------------------------------------
constexpr int BM = 128, BN = 128, BK = 64, STAGES = 3;
constexpr int KDIM = 1024, KT = KDIM / BK;           // 16
constexpr int LDS = BK + 8;                          // 72 halfs / 144B row
constexpr int A_STG = BM * LDS;
constexpr int B_STG = BN * LDS;
constexpr int STG   = A_STG + B_STG;
constexpr int SMEM_BYTES = STAGES * STG * (int)sizeof(__half);   // 110592

template <int EPI>
__device__ __forceinline__ void gemm_core(
    const __half* __restrict__ A,     // [M,1024], offset to row 0
    const __half* __restrict__ W,     // 128 rows x 1024 (this CTA's slab)
    __half* __restrict__ outH,        // col-offset applied by caller
    float* __restrict__ outF,
    const float* __restrict__ bias,   // col-offset applied
    const float* __restrict__ resid,  // col-offset applied, stride ldOut
    int bm, int ldOut)
{
    extern __shared__ __half smem[];

    const int tid  = threadIdx.x;
    const int warp = tid >> 5;
    const int lane = tid & 31;
    const int wm   = (warp & 1) * 64;
    const int wn   = (warp >> 1) * 32;

    float acc[4][4][4];
#pragma unroll
    for (int i = 0; i < 4; i++)
#pragma unroll
        for (int j = 0; j < 4; j++)
#pragma unroll
            for (int l = 0; l < 4; l++) acc[i][j][l] = 0.f;

    auto load_stage = [&](int stage, int kt) {
        const int k0 = kt * BK;
        __half* sa = smem + stage * STG;
        __half* sb = sa + A_STG;
#pragma unroll
        for (int i = 0; i < 8; i++) {
            int id = tid + i * 256;                 // 0..2047
            if (id < 1024) {
                int row = id >> 3, seg = id & 7;
                cp16(smem_u32(sa + row * LDS + seg * 8),
                     A + (size_t)(bm + row) * KDIM + k0 + seg * 8);
            } else {
                id -= 1024;
                int row = id >> 3, seg = id & 7;
                cp16(smem_u32(sb + row * LDS + seg * 8),
                     W + (size_t)row * KDIM + k0 + seg * 8);
            }
        }
    };

#pragma unroll
    for (int s = 0; s < STAGES - 1; s++) { load_stage(s, s); cp_commit(); }

    const int a_row = (lane & 15);
    const int a_col = (lane >> 4) * 8;
    const int b_row = ((lane >> 4) << 3) + (lane & 7);
    const int b_col = ((lane >> 3) & 1) * 8;

    for (int kt = 0; kt < KT; kt++) {
        cp_wait<STAGES - 2>();
        __syncthreads();   // stage kt ready AND all warps done with stage kt-1

        if (kt + STAGES - 1 < KT) load_stage((kt + STAGES - 1) % STAGES, kt + STAGES - 1);
        cp_commit();

        const __half* as = smem + (kt % STAGES) * STG;
        const __half* bs = as + A_STG;

        // B fragment double buffer: bfr[buf][4 n-tiles][2 regs]
        uint32_t bfr[2][8];
        auto loadB = [&](int buf, int kk) {
#pragma unroll
            for (int p = 0; p < 2; p++) {
                uint32_t t[4];
                int r = wn + p * 16 + b_row;
                ldmatrix_x4(t, smem_u32(bs + r * LDS + kk * 16 + b_col));
                bfr[buf][4 * p + 0] = t[0]; bfr[buf][4 * p + 1] = t[1];
                bfr[buf][4 * p + 2] = t[2]; bfr[buf][4 * p + 3] = t[3];
            }
        };

        loadB(0, 0);   // head: only 2 LDSM before first MMA
#pragma unroll
        for (int kk = 0; kk < 4; kk++) {
            const int cur = kk & 1;
            if (kk < 3) loadB(cur ^ 1, kk + 1);      // overlaps with MMAs below
#pragma unroll
            for (int am = 0; am < 4; am++) {
                uint32_t af[4];
                int r = wm + am * 16 + a_row;
                ldmatrix_x4(af, smem_u32(as + r * LDS + kk * 16 + a_col));
#pragma unroll
                for (int an = 0; an < 4; an++)
                    mma16816(acc[am][an], af, &bfr[cur][2 * an]);
            }
        }
        // next iteration's top barrier doubles as the trailing barrier
    }

    // Epilogue
    const int tr = lane >> 2;
    const int tc = (lane & 3) * 2;
#pragma unroll
    for (int am = 0; am < 4; am++) {
#pragma unroll
        for (int an = 0; an < 4; an++) {
            int row0 = bm + wm + am * 16 + tr;
            int cl   = wn + an * 8 + tc;        // local col 0..127
            float* a = acc[am][an];
            float2 bb = *reinterpret_cast<const float2*>(&bias[cl]);
            if (EPI == 0) {
                *reinterpret_cast<__half2*>(&outH[(size_t)row0 * ldOut + cl]) =
                    __floats2half2_rn(a[0] + bb.x, a[1] + bb.y);
                *reinterpret_cast<__half2*>(&outH[(size_t)(row0 + 8) * ldOut + cl]) =
                    __floats2half2_rn(a[2] + bb.x, a[3] + bb.y);
            } else {
                size_t i0 = (size_t)row0 * ldOut + cl;
                size_t i1 = (size_t)(row0 + 8) * ldOut + cl;
                float2 r0 = *reinterpret_cast<const float2*>(&resid[i0]);
                float2 r1 = *reinterpret_cast<const float2*>(&resid[i1]);
                *reinterpret_cast<float2*>(&outF[i0]) =
                    make_float2(a[0] + bb.x + r0.x, a[1] + bb.y + r0.y);
                *reinterpret_cast<float2*>(&outF[i1]) =
                    make_float2(a[2] + bb.x + r1.x, a[3] + bb.y + r1.y);
            }
        }
    }
}

// ---------------------------------------------------------------------------
// Fused QKV projection: one launch covers
//   gx in [0,8)  : Q  = img * Wq^T  + bq   -> g_Q  [16384,1024]
//   gx in [8,24) : KVi = img * Wkv^T + bkv -> g_KV rows [0,16384)   [*,2048]
//   gx in [24,40): KVs = sig * Wkv^T + bkv -> g_KV rows [16384,32768)
// ---------------------------------------------------------------------------
__global__ __launch_bounds__(256, 2) void k_qkv(const float* __restrict__ bq) {
    const int gx = blockIdx.x;
    const int bm = blockIdx.y * BM;

    const __half* A;
    const __half* W;
    __half* out;
    const float* bias;
    int ldOut;

    if (gx < 8) {
        int col0 = gx * 128;
        A = g_AB;  W = g_Wq + (size_t)col0 * KDIM;
        out = g_Q + col0;  bias = bq + col0;  ldOut = 1024;
    } else if (gx < 24) {
        int col0 = (gx - 8) * 128;
        A = g_AB;  W = g_Wkv + (size_t)col0 * KDIM;
        out = g_KV + col0;  bias = g_bkv + col0;  ldOut = 2048;
    } else {
        int col0 = (gx - 24) * 128;
        A = g_AB + (size_t)B_ * E_;  W = g_Wkv + (size_t)col0 * KDIM;
        out = g_KV + (size_t)B_ * 2048 + col0;  bias = g_bkv + col0;  ldOut = 2048;
    }
    gemm_core<0>(A, W, out, nullptr, bias, nullptr, bm, ldOut);
}

// ---------------------------------------------------------------------------
// O-projection: fused = ctx * Wo^T + bo + img   (float out)
// ---------------------------------------------------------------------------
__global__ __launch_bounds__(256, 2) void k_ogemm(const float* __restrict__ bo,
                                                  const float* __restrict__ img) {
    const int col0 = blockIdx.x * 128;
    const int bm   = blockIdx.y * BM;
    gemm_core<1>(g_ctx, g_Wo + (size_t)col0 * KDIM, nullptr, g_fused + col0,
                 bo + col0, img + col0, bm, 1024);
}

// ---------------------------------------------------------------------------
// Attention: one warp per (b,h). seq_q=1, seq_kv=2 -> 2-way softmax.
// ---------------------------------------------------------------------------
__global__ void k_attn(const __half* __restrict__ Q, const __half* __restrict__ KV,
                       __half* __restrict__ ctx) {
    int gw   = blockIdx.x * (blockDim.x >> 5) + (threadIdx.x >> 5);
    int lane = threadIdx.x & 31;
    int b = gw >> 3;
    int h = gw & 7;
    if (b >= B_) return;

    const __half2* q2  = reinterpret_cast<const __half2*>(Q  + (size_t)b * E_ + h * D_) + lane * 2;
    const __half2* ki2 = reinterpret_cast<const __half2*>(KV + (size_t)b * 2048 + h * D_) + lane * 2;
    const __half2* vi2 = reinterpret_cast<const __half2*>(KV + (size_t)b * 2048 + 1024 + h * D_) + lane * 2;
    const __half2* ks2 = reinterpret_cast<const __half2*>(KV + (size_t)(B_ + b) * 2048 + h * D_) + lane * 2;
    const __half2* vs2 = reinterpret_cast<const __half2*>(KV + (size_t)(B_ + b) * 2048 + 1024 + h * D_) + lane * 2;

    float2 qa = __half22float2(q2[0]),  qb = __half22float2(q2[1]);
    float2 ka = __half22float2(ki2[0]), kb = __half22float2(ki2[1]);
    float2 sa = __half22float2(ks2[0]), sb = __half22float2(ks2[1]);

    float d0 = qa.x * ka.x + qa.y * ka.y + qb.x * kb.x + qb.y * kb.y;
    float d1 = qa.x * sa.x + qa.y * sa.y + qb.x * sb.x + qb.y * sb.y;
#pragma unroll
    for (int off = 16; off > 0; off >>= 1) {
        d0 += __shfl_xor_sync(0xffffffffu, d0, off);
        d1 += __shfl_xor_sync(0xffffffffu, d1, off);
    }
    const float scale = 0.08838834764831845f;
    d0 *= scale; d1 *= scale;
    float m  = fmaxf(d0, d1);
    float e0 = __expf(d0 - m), e1 = __expf(d1 - m);
    float inv = 1.f / (e0 + e1);
    float a0 = e0 * inv, a1 = e1 * inv;

    float2 va = __half22float2(vi2[0]), vb = __half22float2(vi2[1]);
    float2 wa = __half22float2(vs2[0]), wb = __half22float2(vs2[1]);

    __half2* c2 = reinterpret_cast<__half2*>(ctx + (size_t)b * E_ + h * D_) + lane * 2;
    c2[0] = __floats2half2_rn(a0 * va.x + a1 * wa.x, a0 * va.y + a1 * wa.y);
    c2[1] = __floats2half2_rn(a0 * vb.x + a1 * wb.x, a0 * vb.y + a1 * wb.y);
}

// ---------------------------------------------------------------------------
// LayerNorm: one warp per row of 1024 floats.
// ---------------------------------------------------------------------------
__global__ void k_layernorm(const float* __restrict__ fused,
                            const float* __restrict__ gamma,
                            const float* __restrict__ beta,
                            float* __restrict__ out) {
    int row  = blockIdx.x * (blockDim.x >> 5) + (threadIdx.x >> 5);
    int lane = threadIdx.x & 31;
    if (row >= B_) return;

    const float4* r4 = reinterpret_cast<const float4*>(fused + (size_t)row * E_);
    float4 x[8];
    float s = 0.f, sq = 0.f;
#pragma unroll
    for (int j = 0; j < 8; j++) {
        x[j] = r4[lane + 32 * j];
        s  += x[j].x + x[j].y + x[j].z + x[j].w;
        sq += x[j].x * x[j].x + x[j].y * x[j].y + x[j].z * x[j].z + x[j].w * x[j].w;
    }
#pragma unroll
    for (int off = 16; off > 0; off >>= 1) {
        s  += __shfl_xor_sync(0xffffffffu, s,  off);
        sq += __shfl_xor_sync(0xffffffffu, sq, off);
    }
    float mean = s * (1.f / E_);
    float var  = sq * (1.f / E_) - mean * mean;
    float rstd = rsqrtf(var + 1e-5f);

    float4* o4 = reinterpret_cast<float4*>(out + (size_t)row * E_);
    const float4* g4 = reinterpret_cast<const float4*>(gamma);
    const float4* b4 = reinterpret_cast<const float4*>(beta);
#pragma unroll
    for (int j = 0; j < 8; j++) {
        int c = lane + 32 * j;
        float4 g = g4[c], bb = b4[c], r;
        r.x = (x[j].x - mean) * rstd * g.x + bb.x;
        r.y = (x[j].y - mean) * rstd * g.y + bb.y;
        r.z = (x[j].z - mean) * rstd * g.z + bb.z;
        r.w = (x[j].w - mean) * rstd * g.w + bb.w;
        o4[c] = r;
    }
}

// ---------------------------------------------------------------------------
// kernel_launch
// ---------------------------------------------------------------------------
extern "C" void kernel_launch(void* const* d_in, const int* in_sizes, int n_in,
                              void* d_out, int out_size) {
    const float* img   = (const float*)d_in[0];
    const float* sig   = (const float*)d_in[1];
    const float* wq    = (const float*)d_in[2];
    const float* wk    = (const float*)d_in[3];
    const float* wv    = (const float*)d_in[4];
    const float* bq    = (const float*)d_in[5];
    const float* bk    = (const float*)d_in[6];
    const float* bv    = (const float*)d_in[7];
    const float* wo    = (const float*)d_in[8];
    const float* bo    = (const float*)d_in[9];
    const float* gamma = (const float*)d_in[10];
    const float* beta  = (const float*)d_in[11];
    float* out = (float*)d_out;

    void *pQ, *pKV, *pCtx, *pFused;
    cudaGetSymbolAddress(&pQ,     g_Q);
    cudaGetSymbolAddress(&pKV,    g_KV);
    cudaGetSymbolAddress(&pCtx,   g_ctx);
    cudaGetSymbolAddress(&pFused, g_fused);

    cudaFuncSetAttribute(k_qkv,   cudaFuncAttributeMaxDynamicSharedMemorySize, SMEM_BYTES);
    cudaFuncSetAttribute(k_ogemm, cudaFuncAttributeMaxDynamicSharedMemorySize, SMEM_BYTES);

    // 1) all conversions in one launch
    k_convert_all<<<CVT_TOT / 256, 256>>>(img, sig, wq, wk, wv, wo, bk, bv);

    // 2) fused QKV projections (Q + img-KV + sig-KV) in one launch
    k_qkv<<<dim3(40, B_ / BM), 256, SMEM_BYTES>>>(bq);

    // 3) attention -> ctx
    k_attn<<<(B_ * H_) / 8, 256>>>((const __half*)pQ, (const __half*)pKV, (__half*)pCtx);

    // 4) fused = ctx * Wo^T + bo + img (float)
    k_ogemm<<<dim3(E_ / BN, B_ / BM), 256, SMEM_BYTES>>>(bo, img);

    // 5) LayerNorm -> out
    k_layernorm<<<B_ / 8, 256>>>((const float*)pFused, gamma, beta, out);
}

// round 7
// speedup vs baseline: 1.0809x; 1.0809x over previous
#include <cuda_runtime.h>
#include <cuda_fp16.h>
#include <cstdint>

// Problem constants
constexpr int B_ = 16384;
constexpr int E_ = 1024;
constexpr int H_ = 8;
constexpr int D_ = 128;

// ---------------------------------------------------------------------------
// Scratch (static device globals: allocation-free, graph-capture safe)
// ---------------------------------------------------------------------------
__device__ __half g_AB[2u * B_ * E_];           // [image; signal] fp16   (64 MB)
__device__ __half g_Wq[E_ * E_];
__device__ __half g_Wk[E_ * E_];
__device__ __half g_Wv[E_ * E_];
__device__ __half g_Wo[E_ * E_];
__device__ __half g_Q[(size_t)B_ * E_];         // q proj                 (32 MB)
__device__ __half g_K[(size_t)2 * B_ * E_];     // [k_img; k_sig]         (64 MB)
__device__ float  g_attw[(size_t)B_ * H_];      // a0 per (b,h)           (0.5MB)
__device__ __half g_ctx[(size_t)B_ * E_];       //                        (32 MB)
__device__ float  g_fused[(size_t)B_ * E_];     // attn_out + residual    (64 MB)

// ---------------------------------------------------------------------------
// PTX helpers (sm_80-class only: cp.async / ldmatrix / mma.sync)
// ---------------------------------------------------------------------------
__device__ __forceinline__ uint32_t smem_u32(const void* p) {
    return (uint32_t)__cvta_generic_to_shared(p);
}
__device__ __forceinline__ void cp16(uint32_t s, const void* g) {
    asm volatile("cp.async.cg.shared.global [%0], [%1], 16;\n" :: "r"(s), "l"(g));
}
__device__ __forceinline__ void cp_commit() {
    asm volatile("cp.async.commit_group;\n");
}
template <int N>
__device__ __forceinline__ void cp_wait() {
    asm volatile("cp.async.wait_group %0;\n" :: "n"(N));
}
__device__ __forceinline__ void ldmatrix_x4(uint32_t* r, uint32_t addr) {
    asm volatile("ldmatrix.sync.aligned.m8n8.x4.shared.b16 {%0,%1,%2,%3}, [%4];\n"
                 : "=r"(r[0]), "=r"(r[1]), "=r"(r[2]), "=r"(r[3]) : "r"(addr));
}
__device__ __forceinline__ void mma16816(float* c, const uint32_t* a, const uint32_t* b) {
    asm volatile("mma.sync.aligned.m16n8k16.row.col.f32.f16.f16.f32 "
                 "{%0,%1,%2,%3}, {%4,%5,%6,%7}, {%8,%9}, {%0,%1,%2,%3};\n"
                 : "+f"(c[0]), "+f"(c[1]), "+f"(c[2]), "+f"(c[3])
                 : "r"(a[0]), "r"(a[1]), "r"(a[2]), "r"(a[3]), "r"(b[0]), "r"(b[1]));
}

// ---------------------------------------------------------------------------
// Single conversion kernel (inputs fp32->fp16, weights fp32->fp16)
// ---------------------------------------------------------------------------
constexpr int IN4 = (2 * B_ * E_) / 4;        // 8388608
constexpr int W4  = (4 * E_ * E_) / 4;        // 1048576
constexpr int CVT_TOT = IN4 + W4;             // divisible by 256

__global__ void k_convert_all(const float* __restrict__ img, const float* __restrict__ sig,
                              const float* __restrict__ wq, const float* __restrict__ wk,
                              const float* __restrict__ wv, const float* __restrict__ wo) {
    int i = blockIdx.x * blockDim.x + threadIdx.x;
    if (i < IN4) {
        const int n4 = (B_ * E_) / 4;
        float4 v = (i < n4) ? reinterpret_cast<const float4*>(img)[i]
                            : reinterpret_cast<const float4*>(sig)[i - n4];
        __half* dst = g_AB + (size_t)4 * i;
        *reinterpret_cast<__half2*>(dst)     = __floats2half2_rn(v.x, v.y);
        *reinterpret_cast<__half2*>(dst + 2) = __floats2half2_rn(v.z, v.w);
    } else {
        int j = i - IN4;
        const int per = (E_ * E_) / 4;
        int m = j / per;
        int t = j - m * per;
        const float* src;
        __half* dst;
        if (m == 0)      { src = wq; dst = g_Wq; }
        else if (m == 1) { src = wk; dst = g_Wk; }
        else if (m == 2) { src = wv; dst = g_Wv; }
        else             { src = wo; dst = g_Wo; }
        float4 v = reinterpret_cast<const float4*>(src)[t];
        dst += (size_t)4 * t;
        *reinterpret_cast<__half2*>(dst)     = __floats2half2_rn(v.x, v.y);
        *reinterpret_cast<__half2*>(dst + 2) = __floats2half2_rn(v.z, v.w);
    }
}

// ---------------------------------------------------------------------------
// Shared GEMM core: C[*, cl] = A[M,1024] * W[128 rows,1024]^T (NT), fp16->fp32.
// CTA tile 128x128x64, 3-stage cp.async, 8 warps (2M x 4N), warp 64x32.
// EPI=0: half out = acc + bias[cl];  EPI=1: float out = acc + bias + resid
// ---------------------------------------------------------------------------
constexpr int BM = 128, BN = 128, BK = 64, STAGES = 3;
constexpr int KDIM = 1024, KT = KDIM / BK;           // 16
constexpr int LDS = BK + 8;                          // 72 halfs / 144B row
constexpr int A_STG = BM * LDS;                      // 9216 halfs
constexpr int STG   = 2 * A_STG;
constexpr int SMEM_BYTES = STAGES * STG * (int)sizeof(__half);   // 110592

template <int EPI>
__device__ __forceinline__ void gemm_core(
    const __half* __restrict__ A,
    const __half* __restrict__ W,
    __half* __restrict__ outH,
    float* __restrict__ outF,
    const float* __restrict__ bias,
    const float* __restrict__ resid,
    int bm, int ldOut)
{
    extern __shared__ __half smem[];

    const int tid  = threadIdx.x;
    const int warp = tid >> 5;
    const int lane = tid & 31;
    const int wm   = (warp & 1) * 64;
    const int wn   = (warp >> 1) * 32;

    float acc[4][4][4];
#pragma unroll
    for (int i = 0; i < 4; i++)
#pragma unroll
        for (int j = 0; j < 4; j++)
#pragma unroll
            for (int l = 0; l < 4; l++) acc[i][j][l] = 0.f;

    auto load_stage = [&](int stage, int kt) {
        const int k0 = kt * BK;
        __half* sa = smem + stage * STG;
        __half* sb = sa + A_STG;
#pragma unroll
        for (int i = 0; i < 8; i++) {
            int id = tid + i * 256;
            if (id < 1024) {
                int row = id >> 3, seg = id & 7;
                cp16(smem_u32(sa + row * LDS + seg * 8),
                     A + (size_t)(bm + row) * KDIM + k0 + seg * 8);
            } else {
                id -= 1024;
                int row = id >> 3, seg = id & 7;
                cp16(smem_u32(sb + row * LDS + seg * 8),
                     W + (size_t)row * KDIM + k0 + seg * 8);
            }
        }
    };

#pragma unroll
    for (int s = 0; s < STAGES - 1; s++) { load_stage(s, s); cp_commit(); }

    const int a_row = (lane & 15);
    const int a_col = (lane >> 4) * 8;
    const int b_row = ((lane >> 4) << 3) + (lane & 7);
    const int b_col = ((lane >> 3) & 1) * 8;

    for (int kt = 0; kt < KT; kt++) {
        cp_wait<STAGES - 2>();
        __syncthreads();

        if (kt + STAGES - 1 < KT) load_stage((kt + STAGES - 1) % STAGES, kt + STAGES - 1);
        cp_commit();

        const __half* as = smem + (kt % STAGES) * STG;
        const __half* bs = as + A_STG;

        uint32_t bfr[2][8];
        auto loadB = [&](int buf, int kk) {
#pragma unroll
            for (int p = 0; p < 2; p++) {
                uint32_t t[4];
                int r = wn + p * 16 + b_row;
                ldmatrix_x4(t, smem_u32(bs + r * LDS + kk * 16 + b_col));
                bfr[buf][4 * p + 0] = t[0]; bfr[buf][4 * p + 1] = t[1];
                bfr[buf][4 * p + 2] = t[2]; bfr[buf][4 * p + 3] = t[3];
            }
        };

        loadB(0, 0);
#pragma unroll
        for (int kk = 0; kk < 4; kk++) {
            const int cur = kk & 1;
            if (kk < 3) loadB(cur ^ 1, kk + 1);
#pragma unroll
            for (int am = 0; am < 4; am++) {
                uint32_t af[4];
                int r = wm + am * 16 + a_row;
                ldmatrix_x4(af, smem_u32(as + r * LDS + kk * 16 + a_col));
#pragma unroll
                for (int an = 0; an < 4; an++)
                    mma16816(acc[am][an], af, &bfr[cur][2 * an]);
            }
        }
    }

    // Epilogue
    const int tr = lane >> 2;
    const int tc = (lane & 3) * 2;
#pragma unroll
    for (int am = 0; am < 4; am++) {
#pragma unroll
        for (int an = 0; an < 4; an++) {
            int row0 = bm + wm + am * 16 + tr;
            int cl   = wn + an * 8 + tc;
            float* a = acc[am][an];
            float2 bb = *reinterpret_cast<const float2*>(&bias[cl]);
            if (EPI == 0) {
                *reinterpret_cast<__half2*>(&outH[(size_t)row0 * ldOut + cl]) =
                    __floats2half2_rn(a[0] + bb.x, a[1] + bb.y);
                *reinterpret_cast<__half2*>(&outH[(size_t)(row0 + 8) * ldOut + cl]) =
                    __floats2half2_rn(a[2] + bb.x, a[3] + bb.y);
            } else {
                size_t i0 = (size_t)row0 * ldOut + cl;
                size_t i1 = (size_t)(row0 + 8) * ldOut + cl;
                float2 r0 = *reinterpret_cast<const float2*>(&resid[i0]);
                float2 r1 = *reinterpret_cast<const float2*>(&resid[i1]);
                *reinterpret_cast<float2*>(&outF[i0]) =
                    make_float2(a[0] + bb.x + r0.x, a[1] + bb.y + r0.y);
                *reinterpret_cast<float2*>(&outF[i1]) =
                    make_float2(a[2] + bb.x + r1.x, a[3] + bb.y + r1.y);
            }
        }
    }
}

// ---------------------------------------------------------------------------
// Fused Q/K projections: one launch covers
//   gx in [0,8)  : Q     = img * Wq^T + bq -> g_Q
//   gx in [8,16) : K_img = img * Wk^T + bk -> g_K rows [0,B)
//   gx in [16,24): K_sig = sig * Wk^T + bk -> g_K rows [B,2B)
// ---------------------------------------------------------------------------
__global__ __launch_bounds__(256, 2) void k_qk(const float* __restrict__ bq,
                                               const float* __restrict__ bk) {
    const int gx = blockIdx.x;
    const int bm = blockIdx.y * BM;

    const __half* A;
    const __half* W;
    __half* out;
    const float* bias;

    if (gx < 8) {
        int col0 = gx * 128;
        A = g_AB;  W = g_Wq + (size_t)col0 * KDIM;
        out = g_Q + col0;  bias = bq + col0;
    } else if (gx < 16) {
        int col0 = (gx - 8) * 128;
        A = g_AB;  W = g_Wk + (size_t)col0 * KDIM;
        out = g_K + col0;  bias = bk + col0;
    } else {
        int col0 = (gx - 16) * 128;
        A = g_AB + (size_t)B_ * E_;  W = g_Wk + (size_t)col0 * KDIM;
        out = g_K + (size_t)B_ * E_ + col0;  bias = bk + col0;
    }
    gemm_core<0>(A, W, out, nullptr, bias, nullptr, bm, 1024);
}

// ---------------------------------------------------------------------------
// Scores: one warp per (b,h); 2-way softmax -> a0 weight only.
// ---------------------------------------------------------------------------
__global__ void k_scores(const __half* __restrict__ Q, const __half* __restrict__ K) {
    int gw   = blockIdx.x * (blockDim.x >> 5) + (threadIdx.x >> 5);
    int lane = threadIdx.x & 31;
    int b = gw >> 3;
    int h = gw & 7;
    if (b >= B_) return;

    const __half2* q2  = reinterpret_cast<const __half2*>(Q + (size_t)b * E_ + h * D_) + lane * 2;
    const __half2* ki2 = reinterpret_cast<const __half2*>(K + (size_t)b * E_ + h * D_) + lane * 2;
    const __half2* ks2 = reinterpret_cast<const __half2*>(K + (size_t)(B_ + b) * E_ + h * D_) + lane * 2;

    float2 qa = __half22float2(q2[0]),  qb = __half22float2(q2[1]);
    float2 ka = __half22float2(ki2[0]), kb = __half22float2(ki2[1]);
    float2 sa = __half22float2(ks2[0]), sb = __half22float2(ks2[1]);

    float d0 = qa.x * ka.x + qa.y * ka.y + qb.x * kb.x + qb.y * kb.y;
    float d1 = qa.x * sa.x + qa.y * sa.y + qb.x * sb.x + qb.y * sb.y;
#pragma unroll
    for (int off = 16; off > 0; off >>= 1) {
        d0 += __shfl_xor_sync(0xffffffffu, d0, off);
        d1 += __shfl_xor_sync(0xffffffffu, d1, off);
    }
    const float scale = 0.08838834764831845f;   // 1/sqrt(128)
    d0 *= scale; d1 *= scale;
    float m  = fmaxf(d0, d1);
    float e0 = __expf(d0 - m), e1 = __expf(d1 - m);
    float a0 = e0 / (e0 + e1);
    if (lane == 0) g_attw[(size_t)b * H_ + h] = a0;
}

// ---------------------------------------------------------------------------
// Fused V-projection + attention combine:
//   ctx[:, h*128:(h+1)*128] = (a0_h*img + (1-a0_h)*sig) * Wv_h^T + bv_h
// A tiles (img & sig) both staged; mixing done on fragments with per-row
// half2 coefficients (fma pipe, overlaps tensor). 2-stage cp.async.
// ---------------------------------------------------------------------------
constexpr int V_STGH = 3 * A_STG;                    // img + sig + B
constexpr int V_SMEM = 2 * V_STGH * (int)sizeof(__half);  // 110592

__global__ __launch_bounds__(256, 2) void k_vgemm(const float* __restrict__ bv) {
    extern __shared__ __half smem[];

    const int h  = blockIdx.x;
    const int bm = blockIdx.y * BM;
    const int tid  = threadIdx.x;
    const int warp = tid >> 5;
    const int lane = tid & 31;
    const int wm   = (warp & 1) * 64;
    const int wn   = (warp >> 1) * 32;

    const __half* Aimg = g_AB;
    const __half* Asig = g_AB + (size_t)B_ * E_;
    const __half* W    = g_Wv + (size_t)h * 128 * KDIM;

    float acc[4][4][4];
#pragma unroll
    for (int i = 0; i < 4; i++)
#pragma unroll
        for (int j = 0; j < 4; j++)
#pragma unroll
            for (int l = 0; l < 4; l++) acc[i][j][l] = 0.f;

    // per-row mixing coefficients (fragment rows g and g+8 per am)
    uint32_t c0[4][2], c1[4][2];
    {
        const int g = lane >> 2;
#pragma unroll
        for (int am = 0; am < 4; am++) {
            int r0 = bm + wm + am * 16 + g;
            float ca = g_attw[(size_t)r0 * H_ + h];
            float cb = g_attw[(size_t)(r0 + 8) * H_ + h];
            __half2 t;
            t = __float2half2_rn(ca);       c0[am][0] = *reinterpret_cast<uint32_t*>(&t);
            t = __float2half2_rn(1.f - ca); c1[am][0] = *reinterpret_cast<uint32_t*>(&t);
            t = __float2half2_rn(cb);       c0[am][1] = *reinterpret_cast<uint32_t*>(&t);
            t = __float2half2_rn(1.f - cb); c1[am][1] = *reinterpret_cast<uint32_t*>(&t);
        }
    }

    auto load_stage = [&](int stage, int kt) {
        const int k0 = kt * BK;
        __half* si = smem + stage * V_STGH;
        __half* ss = si + A_STG;
        __half* sb = si + 2 * A_STG;
#pragma unroll
        for (int i = 0; i < 12; i++) {
            int id = tid + i * 256;                  // 0..3071
            int row = (id & 1023) >> 3, seg = id & 7;
            if (id < 1024)
                cp16(smem_u32(si + row * LDS + seg * 8),
                     Aimg + (size_t)(bm + row) * KDIM + k0 + seg * 8);
            else if (id < 2048)
                cp16(smem_u32(ss + row * LDS + seg * 8),
                     Asig + (size_t)(bm + row) * KDIM + k0 + seg * 8);
            else
                cp16(smem_u32(sb + row * LDS + seg * 8),
                     W + (size_t)row * KDIM + k0 + seg * 8);
        }
    };

    load_stage(0, 0);
    cp_commit();

    const int a_row = (lane & 15);
    const int a_col = (lane >> 4) * 8;
    const int b_row = ((lane >> 4) << 3) + (lane & 7);
    const int b_col = ((lane >> 3) & 1) * 8;

    for (int kt = 0; kt < KT; kt++) {
        cp_wait<0>();
        __syncthreads();

        if (kt + 1 < KT) load_stage((kt + 1) & 1, kt + 1);
        cp_commit();

        const __half* ai = smem + (kt & 1) * V_STGH;
        const __half* as = ai + A_STG;
        const __half* bs = ai + 2 * A_STG;

#pragma unroll
        for (int kk = 0; kk < 4; kk++) {
            uint32_t bfr[8];
#pragma unroll
            for (int p = 0; p < 2; p++) {
                uint32_t t[4];
                int r = wn + p * 16 + b_row;
                ldmatrix_x4(t, smem_u32(bs + r * LDS + kk * 16 + b_col));
                bfr[4 * p + 0] = t[0]; bfr[4 * p + 1] = t[1];
                bfr[4 * p + 2] = t[2]; bfr[4 * p + 3] = t[3];
            }
#pragma unroll
            for (int am = 0; am < 4; am++) {
                uint32_t fi[4], fs[4], af[4];
                int r = wm + am * 16 + a_row;
                ldmatrix_x4(fi, smem_u32(ai + r * LDS + kk * 16 + a_col));
                ldmatrix_x4(fs, smem_u32(as + r * LDS + kk * 16 + a_col));
#pragma unroll
                for (int j = 0; j < 4; j++) {
                    const int half_sel = j & 1;      // regs 0,2 -> row g; 1,3 -> g+8
                    __half2 i2 = *reinterpret_cast<__half2*>(&fi[j]);
                    __half2 s2 = *reinterpret_cast<__half2*>(&fs[j]);
                    __half2 cc0 = *reinterpret_cast<__half2*>(&c0[am][half_sel]);
                    __half2 cc1 = *reinterpret_cast<__half2*>(&c1[am][half_sel]);
                    __half2 mx = __hfma2(i2, cc0, __hmul2(s2, cc1));
                    af[j] = *reinterpret_cast<uint32_t*>(&mx);
                }
#pragma unroll
                for (int an = 0; an < 4; an++)
                    mma16816(acc[am][an], af, &bfr[2 * an]);
            }
        }
    }

    // Epilogue -> g_ctx (half), bias = bv slice
    const int tr = lane >> 2;
    const int tc = (lane & 3) * 2;
    const float* bh = bv + h * 128;
    __half* outH = g_ctx + h * 128;
#pragma unroll
    for (int am = 0; am < 4; am++) {
#pragma unroll
        for (int an = 0; an < 4; an++) {
            int row0 = bm + wm + am * 16 + tr;
            int cl   = wn + an * 8 + tc;
            float* a = acc[am][an];
            float2 bb = *reinterpret_cast<const float2*>(&bh[cl]);
            *reinterpret_cast<__half2*>(&outH[(size_t)row0 * 1024 + cl]) =
                __floats2half2_rn(a[0] + bb.x, a[1] + bb.y);
            *reinterpret_cast<__half2*>(&outH[(size_t)(row0 + 8) * 1024 + cl]) =
                __floats2half2_rn(a[2] + bb.x, a[3] + bb.y);
        }
    }
}

// ---------------------------------------------------------------------------
// O-projection: fused = ctx * Wo^T + bo + img   (float out)
// ---------------------------------------------------------------------------
__global__ __launch_bounds__(256, 2) void k_ogemm(const float* __restrict__ bo,
                                                  const float* __restrict__ img) {
    const int col0 = blockIdx.x * 128;
    const int bm   = blockIdx.y * BM;
    gemm_core<1>(g_ctx, g_Wo + (size_t)col0 * KDIM, nullptr, g_fused + col0,
                 bo + col0, img + col0, bm, 1024);
}

// ---------------------------------------------------------------------------
// LayerNorm: one warp per row of 1024 floats.
// ---------------------------------------------------------------------------
__global__ void k_layernorm(const float* __restrict__ fused,
                            const float* __restrict__ gamma,
                            const float* __restrict__ beta,
                            float* __restrict__ out) {
    int row  = blockIdx.x * (blockDim.x >> 5) + (threadIdx.x >> 5);
    int lane = threadIdx.x & 31;
    if (row >= B_) return;

    const float4* r4 = reinterpret_cast<const float4*>(fused + (size_t)row * E_);
    float4 x[8];
    float s = 0.f, sq = 0.f;
#pragma unroll
    for (int j = 0; j < 8; j++) {
        x[j] = r4[lane + 32 * j];
        s  += x[j].x + x[j].y + x[j].z + x[j].w;
        sq += x[j].x * x[j].x + x[j].y * x[j].y + x[j].z * x[j].z + x[j].w * x[j].w;
    }
#pragma unroll
    for (int off = 16; off > 0; off >>= 1) {
        s  += __shfl_xor_sync(0xffffffffu, s,  off);
        sq += __shfl_xor_sync(0xffffffffu, sq, off);
    }
    float mean = s * (1.f / E_);
    float var  = sq * (1.f / E_) - mean * mean;
    float rstd = rsqrtf(var + 1e-5f);

    float4* o4 = reinterpret_cast<float4*>(out + (size_t)row * E_);
    const float4* g4 = reinterpret_cast<const float4*>(gamma);
    const float4* b4 = reinterpret_cast<const float4*>(beta);
#pragma unroll
    for (int j = 0; j < 8; j++) {
        int c = lane + 32 * j;
        float4 g = g4[c], bb = b4[c], r;
        r.x = (x[j].x - mean) * rstd * g.x + bb.x;
        r.y = (x[j].y - mean) * rstd * g.y + bb.y;
        r.z = (x[j].z - mean) * rstd * g.z + bb.z;
        r.w = (x[j].w - mean) * rstd * g.w + bb.w;
        o4[c] = r;
    }
}

// ---------------------------------------------------------------------------
// kernel_launch
// ---------------------------------------------------------------------------
extern "C" void kernel_launch(void* const* d_in, const int* in_sizes, int n_in,
                              void* d_out, int out_size) {
    const float* img   = (const float*)d_in[0];
    const float* sig   = (const float*)d_in[1];
    const float* wq    = (const float*)d_in[2];
    const float* wk    = (const float*)d_in[3];
    const float* wv    = (const float*)d_in[4];
    const float* bq    = (const float*)d_in[5];
    const float* bk    = (const float*)d_in[6];
    const float* bv    = (const float*)d_in[7];
    const float* wo    = (const float*)d_in[8];
    const float* bo    = (const float*)d_in[9];
    const float* gamma = (const float*)d_in[10];
    const float* beta  = (const float*)d_in[11];
    float* out = (float*)d_out;

    void *pQ, *pK, *pFused;
    cudaGetSymbolAddress(&pQ,     g_Q);
    cudaGetSymbolAddress(&pK,     g_K);
    cudaGetSymbolAddress(&pFused, g_fused);

    cudaFuncSetAttribute(k_qk,    cudaFuncAttributeMaxDynamicSharedMemorySize, SMEM_BYTES);
    cudaFuncSetAttribute(k_vgemm, cudaFuncAttributeMaxDynamicSharedMemorySize, V_SMEM);
    cudaFuncSetAttribute(k_ogemm, cudaFuncAttributeMaxDynamicSharedMemorySize, SMEM_BYTES);

    // 1) conversions
    k_convert_all<<<CVT_TOT / 256, 256>>>(img, sig, wq, wk, wv, wo);

    // 2) Q + K_img + K_sig projections (3 GEMM units, one launch)
    k_qk<<<dim3(24, B_ / BM), 256, SMEM_BYTES>>>(bq, bk);

    // 3) attention weights a0[b,h]
    k_scores<<<(B_ * H_) / 8, 256>>>((const __half*)pQ, (const __half*)pK);

    // 4) fused V-projection + combine -> ctx (1 GEMM unit instead of 2+attn)
    k_vgemm<<<dim3(H_, B_ / BM), 256, V_SMEM>>>(bv);

    // 5) fused = ctx * Wo^T + bo + img (float)
    k_ogemm<<<dim3(E_ / BN, B_ / BM), 256, SMEM_BYTES>>>(bo, img);

    // 6) LayerNorm -> out
    k_layernorm<<<B_ / 8, 256>>>((const float*)pFused, gamma, beta, out);
}